// round 3
// baseline (speedup 1.0000x reference)
#include <cuda_runtime.h>
#include <cstdint>
#include <cstddef>

// ---------------------------------------------------------------------------
// GraphSAGE 2-layer, sm_103a.
//   h   = relu( scatter_mean(x, src->dst) @ Wl1^T + bl1 + x @ Wr1^T )
//   out =       scatter_mean(h, src->dst) @ Wl2^T + bl2 + h @ Wr2^T
// Round 2: CSR binning + atomic-free gather-mean (replaces RED.v4 scatter).
// ---------------------------------------------------------------------------

#define MAX_N 100000
#define MAX_E 1600000
#define D_IN  128
#define D_HID 128
#define D_OUT 64

// Scratch (device globals: no allocation allowed in kernel_launch)
__device__ float g_agg[(size_t)MAX_N * 128];
__device__ float g_h[(size_t)MAX_N * 128];
__device__ int   g_src[MAX_E];
__device__ int   g_dst[MAX_E];
__device__ int   g_bin[MAX_E];        // src ids grouped by dst
__device__ int   g_cnt[MAX_N + 1];
__device__ int   g_off[MAX_N + 1];
__device__ int   g_cur[MAX_N + 1];
__device__ int   g_bsum[128];
__device__ int   g_is64;

// ---------------------------------------------------------------------------
// Edge-index dtype detection (int64 vs int32 payload).
// ---------------------------------------------------------------------------
__global__ void detect_idx_kernel(const long long* __restrict__ ei, int E, long long N) {
    __shared__ int bad;
    if (threadIdx.x == 0) bad = 0;
    __syncthreads();
    int i = threadIdx.x;
    if (i < E) {
        long long v = ei[i];
        if (v < 0 || v >= N) atomicAdd(&bad, 1);
    }
    __syncthreads();
    if (threadIdx.x == 0) g_is64 = (bad == 0) ? 1 : 0;
}

__global__ void convert_idx_kernel(const void* __restrict__ ei, int E,
                                   int* __restrict__ src, int* __restrict__ dst) {
    int i = blockIdx.x * blockDim.x + threadIdx.x;
    if (i >= E) return;
    if (g_is64) {
        const long long* p = (const long long*)ei;
        src[i] = (int)p[i];
        dst[i] = (int)p[(size_t)E + i];
    } else {
        const int* p = (const int*)ei;
        src[i] = p[i];
        dst[i] = p[(size_t)E + i];
    }
}

// ---------------------------------------------------------------------------
// CSR binning: count -> exclusive scan -> fill
// ---------------------------------------------------------------------------
__global__ void count_kernel(const int* __restrict__ dst, int* __restrict__ cnt, int E) {
    int i = blockIdx.x * blockDim.x + threadIdx.x;
    if (i < E) atomicAdd(&cnt[dst[i]], 1);
}

__global__ void scan_block_kernel(const int* __restrict__ cnt, int* __restrict__ off,
                                  int* __restrict__ bsum, int N) {
    __shared__ int sm[1024];
    int tid = threadIdx.x;
    int gi  = blockIdx.x * 1024 + tid;
    int v   = (gi < N) ? cnt[gi] : 0;
    sm[tid] = v;
    __syncthreads();
#pragma unroll
    for (int s = 1; s < 1024; s <<= 1) {
        int t = (tid >= s) ? sm[tid - s] : 0;
        __syncthreads();
        sm[tid] += t;
        __syncthreads();
    }
    if (gi < N) off[gi] = sm[tid] - v;     // exclusive
    if (tid == 1023) bsum[blockIdx.x] = sm[1023];
}

__global__ void scan_bsum_kernel(int* __restrict__ bsum, int nb) {
    if (threadIdx.x == 0) {
        int run = 0;
        for (int i = 0; i < nb; i++) { int t = bsum[i]; bsum[i] = run; run += t; }
    }
}

__global__ void add_off_kernel(int* __restrict__ off, const int* __restrict__ bsum,
                               int N, int E) {
    int gi = blockIdx.x * blockDim.x + threadIdx.x;
    if (gi < N) off[gi] += bsum[gi >> 10];
    if (gi == 0) off[N] = E;
}

__global__ void fill_kernel(const int* __restrict__ src, const int* __restrict__ dst,
                            int* __restrict__ cur, int* __restrict__ bin, int E) {
    int i = blockIdx.x * blockDim.x + threadIdx.x;
    if (i >= E) return;
    int pos = atomicAdd(&cur[dst[i]], 1);
    bin[pos] = src[i];
}

// ---------------------------------------------------------------------------
// Gather-mean: one warp per dst node; lane owns one float4 of the 128-wide row.
// No atomics; scale by 1/deg folded in.
// ---------------------------------------------------------------------------
__global__ void gather_kernel(const float4* __restrict__ feat,
                              const int* __restrict__ off,
                              const int* __restrict__ bin,
                              float4* __restrict__ agg, int N) {
    int warp = (blockIdx.x * blockDim.x + threadIdx.x) >> 5;
    int lane = threadIdx.x & 31;
    if (warp >= N) return;
    int s0 = off[warp], s1 = off[warp + 1];
    float4 acc = make_float4(0.f, 0.f, 0.f, 0.f);
    int e = s0;
    for (; e + 4 <= s1; e += 4) {
        int i0 = bin[e], i1 = bin[e + 1], i2 = bin[e + 2], i3 = bin[e + 3];
        float4 v0 = feat[(size_t)i0 * 32 + lane];
        float4 v1 = feat[(size_t)i1 * 32 + lane];
        float4 v2 = feat[(size_t)i2 * 32 + lane];
        float4 v3 = feat[(size_t)i3 * 32 + lane];
        acc.x += v0.x + v1.x + v2.x + v3.x;
        acc.y += v0.y + v1.y + v2.y + v3.y;
        acc.z += v0.z + v1.z + v2.z + v3.z;
        acc.w += v0.w + v1.w + v2.w + v3.w;
    }
    for (; e < s1; e++) {
        float4 v = feat[(size_t)bin[e] * 32 + lane];
        acc.x += v.x; acc.y += v.y; acc.z += v.z; acc.w += v.w;
    }
    float sc = 1.0f / (float)max(s1 - s0, 1);
    acc.x *= sc; acc.y *= sc; acc.z *= sc; acc.w *= sc;
    agg[(size_t)warp * 32 + lane] = acc;
}

// ---------------------------------------------------------------------------
// Fused dual GEMM:  out[n, 0:TN] = agg[n] @ Wl^T + x[n] @ Wr^T + b
// One K=256 GEMM with A = [agg | x], W stacked in smem. TM=128, KC=64 dbuf,
// 8x8 register tiles; A-tile k-major so both fragments are LDS.128.
// ---------------------------------------------------------------------------
template <int TN>
__global__ void __launch_bounds__((128 / 8) * (TN / 8))
sage_gemm_kernel(const float* __restrict__ agg,
                 const float* __restrict__ xin,
                 const float* __restrict__ Wl, const float* __restrict__ Wr,
                 const float* __restrict__ bias,
                 float* __restrict__ out, int N, int do_relu) {
    constexpr int TM   = 128;
    constexpr int KC   = 64;
    constexpr int NT   = (TM / 8) * (TN / 8);
    constexpr int WROW = TN + 4;
    constexpr int AROW = TM + 4;

    extern __shared__ float smem[];
    float* Wc = smem;                      // [256][WROW]
    float* At = smem + 256 * WROW;         // [2][KC][AROW]

    const int tid   = threadIdx.x;
    const int node0 = blockIdx.x * TM;

    for (int idx = tid; idx < 128 * TN; idx += NT) {
        int j = idx >> 7;
        int k = idx & 127;
        Wc[k * WROW + j]         = Wl[idx];
        Wc[(128 + k) * WROW + j] = Wr[idx];
    }

    const int cg = tid % (TN / 8);
    const int ng = tid / (TN / 8);

    float acc[8][8];
#pragma unroll
    for (int i = 0; i < 8; i++)
#pragma unroll
        for (int j = 0; j < 8; j++) acc[i][j] = 0.0f;

    auto loadA = [&](int buf, int kc) {
        float* db = At + buf * (KC * AROW);
#pragma unroll 4
        for (int idx = tid; idx < KC * TM; idx += NT) {
            int kk   = idx & (KC - 1);
            int node = idx >> 6;
            int k    = kc * KC + kk;
            int n    = node0 + node;
            float v  = 0.0f;
            if (n < N) {
                v = (k < 128) ? agg[(size_t)n * 128 + k]
                              : xin[(size_t)n * 128 + (k - 128)];
            }
            db[kk * AROW + node] = v;
        }
    };

    loadA(0, 0);
    __syncthreads();

#pragma unroll 1
    for (int kc = 0; kc < 4; kc++) {
        int b = kc & 1;
        if (kc < 3) loadA(b ^ 1, kc + 1);
        const float* Ab = At + b * (KC * AROW);
        const float* Wb = Wc + (kc * KC) * WROW;
#pragma unroll 8
        for (int kk = 0; kk < KC; kk++) {
            float a[8], w[8];
            float4 t;
            t = *(const float4*)(Ab + kk * AROW + ng * 8);
            a[0] = t.x; a[1] = t.y; a[2] = t.z; a[3] = t.w;
            t = *(const float4*)(Ab + kk * AROW + ng * 8 + 4);
            a[4] = t.x; a[5] = t.y; a[6] = t.z; a[7] = t.w;
            t = *(const float4*)(Wb + kk * WROW + cg * 8);
            w[0] = t.x; w[1] = t.y; w[2] = t.z; w[3] = t.w;
            t = *(const float4*)(Wb + kk * WROW + cg * 8 + 4);
            w[4] = t.x; w[5] = t.y; w[6] = t.z; w[7] = t.w;
#pragma unroll
            for (int i = 0; i < 8; i++)
#pragma unroll
                for (int j = 0; j < 8; j++) acc[i][j] += a[i] * w[j];
        }
        __syncthreads();
    }

    float bv[8];
#pragma unroll
    for (int j = 0; j < 8; j++) bv[j] = bias[cg * 8 + j];

#pragma unroll
    for (int i = 0; i < 8; i++) {
        int n = node0 + ng * 8 + i;
        if (n < N) {
            float r[8];
#pragma unroll
            for (int j = 0; j < 8; j++) {
                float v = acc[i][j] + bv[j];
                r[j] = do_relu ? fmaxf(v, 0.0f) : v;
            }
            *(float4*)(out + (size_t)n * TN + cg * 8)     = make_float4(r[0], r[1], r[2], r[3]);
            *(float4*)(out + (size_t)n * TN + cg * 8 + 4) = make_float4(r[4], r[5], r[6], r[7]);
        }
    }
}

// ---------------------------------------------------------------------------

extern "C" void kernel_launch(void* const* d_in, const int* in_sizes, int n_in,
                              void* d_out, int out_size) {
    const float* x   = (const float*)d_in[0];
    const void*  ei  = d_in[1];
    const float* Wl1 = (const float*)d_in[2];
    const float* bl1 = (const float*)d_in[3];
    const float* Wr1 = (const float*)d_in[4];
    const float* Wl2 = (const float*)d_in[5];
    const float* bl2 = (const float*)d_in[6];
    const float* Wr2 = (const float*)d_in[7];
    float* out = (float*)d_out;

    int N = in_sizes[0] / D_IN;
    int E = in_sizes[1] / 2;

    float *agg, *h;
    int *src, *dst, *bin, *cnt, *off, *cur, *bsum;
    cudaGetSymbolAddress((void**)&agg,  g_agg);
    cudaGetSymbolAddress((void**)&h,    g_h);
    cudaGetSymbolAddress((void**)&src,  g_src);
    cudaGetSymbolAddress((void**)&dst,  g_dst);
    cudaGetSymbolAddress((void**)&bin,  g_bin);
    cudaGetSymbolAddress((void**)&cnt,  g_cnt);
    cudaGetSymbolAddress((void**)&off,  g_off);
    cudaGetSymbolAddress((void**)&cur,  g_cur);
    cudaGetSymbolAddress((void**)&bsum, g_bsum);

    constexpr int SMEM1 = (256 * (128 + 4) + 2 * 64 * (128 + 4)) * 4;  // 202752 B
    constexpr int SMEM2 = (256 * (64 + 4)  + 2 * 64 * (128 + 4)) * 4;  // 137216 B
    cudaFuncSetAttribute(sage_gemm_kernel<128>, cudaFuncAttributeMaxDynamicSharedMemorySize, SMEM1);
    cudaFuncSetAttribute(sage_gemm_kernel<64>,  cudaFuncAttributeMaxDynamicSharedMemorySize, SMEM2);

    const int TB = 256;
    int nbE = (E + TB - 1) / TB;
    int nbScan = (N + 1023) / 1024;

    // --- edge normalization + CSR binning (shared by both layers) ---
    detect_idx_kernel<<<1, 256>>>((const long long*)ei, E, (long long)N);
    convert_idx_kernel<<<nbE, TB>>>(ei, E, src, dst);
    cudaMemsetAsync(cnt, 0, (size_t)(N + 1) * sizeof(int));
    count_kernel<<<nbE, TB>>>(dst, cnt, E);
    scan_block_kernel<<<nbScan, 1024>>>(cnt, off, bsum, N);
    scan_bsum_kernel<<<1, 32>>>(bsum, nbScan);
    add_off_kernel<<<(N + TB - 1) / TB, TB>>>(off, bsum, N, E);
    cudaMemcpyAsync(cur, off, (size_t)(N + 1) * sizeof(int), cudaMemcpyDeviceToDevice);
    fill_kernel<<<nbE, TB>>>(src, dst, cur, bin, E);

    int nbGather = (N * 32 + TB - 1) / TB;

    // --- layer 1 ---
    gather_kernel<<<nbGather, TB>>>((const float4*)x, off, bin, (float4*)agg, N);
    sage_gemm_kernel<128><<<(N + 127) / 128, 256, SMEM1>>>(agg, x, Wl1, Wr1, bl1, h, N, 1);

    // --- layer 2 ---
    gather_kernel<<<nbGather, TB>>>((const float4*)h, off, bin, (float4*)agg, N);
    sage_gemm_kernel<64><<<(N + 127) / 128, 128, SMEM2>>>(agg, h, Wl2, Wr2, bl2, out, N, 0);
}

// round 4
// speedup vs baseline: 1.7569x; 1.7569x over previous
#include <cuda_runtime.h>
#include <cstdint>
#include <cstddef>

// ---------------------------------------------------------------------------
// GraphSAGE 2-layer, sm_103a.
//   h   = relu( scatter_mean(x, src->dst) @ Wl1^T + bl1 + x @ Wr1^T )
//   out =       scatter_mean(h, src->dst) @ Wl2^T + bl2 + h @ Wr2^T
// Round 3: GEMM rebuilt on packed fma.rn.f32x2 (FFMA2), k-paired operands.
// ---------------------------------------------------------------------------

#define MAX_N 100000
#define MAX_E 1600000
#define D_IN  128
#define D_HID 128
#define D_OUT 64

typedef unsigned long long ull;

// Scratch (device globals: no allocation allowed in kernel_launch)
__device__ float g_agg[(size_t)MAX_N * 128];
__device__ float g_h[(size_t)MAX_N * 128];
__device__ int   g_src[MAX_E];
__device__ int   g_dst[MAX_E];
__device__ int   g_bin[MAX_E];        // src ids grouped by dst
__device__ int   g_cnt[MAX_N + 1];
__device__ int   g_off[MAX_N + 1];
__device__ int   g_cur[MAX_N + 1];
__device__ int   g_bsum[128];
__device__ int   g_is64;

// ---------------------------------------------------------------------------
__global__ void detect_idx_kernel(const long long* __restrict__ ei, int E, long long N) {
    __shared__ int bad;
    if (threadIdx.x == 0) bad = 0;
    __syncthreads();
    int i = threadIdx.x;
    if (i < E) {
        long long v = ei[i];
        if (v < 0 || v >= N) atomicAdd(&bad, 1);
    }
    __syncthreads();
    if (threadIdx.x == 0) g_is64 = (bad == 0) ? 1 : 0;
}

__global__ void convert_idx_kernel(const void* __restrict__ ei, int E,
                                   int* __restrict__ src, int* __restrict__ dst) {
    int i = blockIdx.x * blockDim.x + threadIdx.x;
    if (i >= E) return;
    if (g_is64) {
        const long long* p = (const long long*)ei;
        src[i] = (int)p[i];
        dst[i] = (int)p[(size_t)E + i];
    } else {
        const int* p = (const int*)ei;
        src[i] = p[i];
        dst[i] = p[(size_t)E + i];
    }
}

// ---------------------------------------------------------------------------
// CSR binning: count -> exclusive scan -> fill
// ---------------------------------------------------------------------------
__global__ void count_kernel(const int* __restrict__ dst, int* __restrict__ cnt, int E) {
    int i = blockIdx.x * blockDim.x + threadIdx.x;
    if (i < E) atomicAdd(&cnt[dst[i]], 1);
}

__global__ void scan_block_kernel(const int* __restrict__ cnt, int* __restrict__ off,
                                  int* __restrict__ bsum, int N) {
    __shared__ int sm[1024];
    int tid = threadIdx.x;
    int gi  = blockIdx.x * 1024 + tid;
    int v   = (gi < N) ? cnt[gi] : 0;
    sm[tid] = v;
    __syncthreads();
#pragma unroll
    for (int s = 1; s < 1024; s <<= 1) {
        int t = (tid >= s) ? sm[tid - s] : 0;
        __syncthreads();
        sm[tid] += t;
        __syncthreads();
    }
    if (gi < N) off[gi] = sm[tid] - v;     // exclusive
    if (tid == 1023) bsum[blockIdx.x] = sm[1023];
}

__global__ void scan_bsum_kernel(int* __restrict__ bsum, int nb) {
    if (threadIdx.x == 0) {
        int run = 0;
        for (int i = 0; i < nb; i++) { int t = bsum[i]; bsum[i] = run; run += t; }
    }
}

__global__ void add_off_kernel(int* __restrict__ off, const int* __restrict__ bsum,
                               int N, int E) {
    int gi = blockIdx.x * blockDim.x + threadIdx.x;
    if (gi < N) off[gi] += bsum[gi >> 10];
    if (gi == 0) off[N] = E;
}

__global__ void fill_kernel(const int* __restrict__ src, const int* __restrict__ dst,
                            int* __restrict__ cur, int* __restrict__ bin, int E) {
    int i = blockIdx.x * blockDim.x + threadIdx.x;
    if (i >= E) return;
    int pos = atomicAdd(&cur[dst[i]], 1);
    bin[pos] = src[i];
}

// ---------------------------------------------------------------------------
// Gather-mean: one warp per dst node; lane owns one float4 of the 128-wide row.
// ---------------------------------------------------------------------------
__global__ void gather_kernel(const float4* __restrict__ feat,
                              const int* __restrict__ off,
                              const int* __restrict__ bin,
                              float4* __restrict__ agg, int N) {
    int warp = (blockIdx.x * blockDim.x + threadIdx.x) >> 5;
    int lane = threadIdx.x & 31;
    if (warp >= N) return;
    int s0 = off[warp], s1 = off[warp + 1];
    float4 acc = make_float4(0.f, 0.f, 0.f, 0.f);
    int e = s0;
    for (; e + 4 <= s1; e += 4) {
        int i0 = bin[e], i1 = bin[e + 1], i2 = bin[e + 2], i3 = bin[e + 3];
        float4 v0 = feat[(size_t)i0 * 32 + lane];
        float4 v1 = feat[(size_t)i1 * 32 + lane];
        float4 v2 = feat[(size_t)i2 * 32 + lane];
        float4 v3 = feat[(size_t)i3 * 32 + lane];
        acc.x += v0.x + v1.x + v2.x + v3.x;
        acc.y += v0.y + v1.y + v2.y + v3.y;
        acc.z += v0.z + v1.z + v2.z + v3.z;
        acc.w += v0.w + v1.w + v2.w + v3.w;
    }
    for (; e < s1; e++) {
        float4 v = feat[(size_t)bin[e] * 32 + lane];
        acc.x += v.x; acc.y += v.y; acc.z += v.z; acc.w += v.w;
    }
    float sc = 1.0f / (float)max(s1 - s0, 1);
    acc.x *= sc; acc.y *= sc; acc.z *= sc; acc.w *= sc;
    agg[(size_t)warp * 32 + lane] = acc;
}

// ---------------------------------------------------------------------------
// Fused dual GEMM on packed fp32 (fma.rn.f32x2), K paired: each 64-bit
// accumulator holds (sum over even k, sum over odd k); summed in epilogue.
//   A = [agg | x]  (K=256), W = [Wl ; Wr] stacked, both staged k-paired.
// TM=128 nodes/CTA. Thread tile: 4 rows x 8 cols. lane->rows, warp->cols.
// ---------------------------------------------------------------------------
__device__ __forceinline__ void ffma2(ull& d, ull a, ull b) {
    asm("fma.rn.f32x2 %0, %1, %2, %3;" : "=l"(d) : "l"(a), "l"(b), "l"(d));
}

template <int TN>
__global__ void __launch_bounds__(32 * (TN / 8), 1)
sage_gemm_kernel(const float* __restrict__ agg,
                 const float* __restrict__ xin,
                 const float* __restrict__ Wl, const float* __restrict__ Wr,
                 const float* __restrict__ bias,
                 float* __restrict__ out, int N, int do_relu) {
    constexpr int TM     = 128;
    constexpr int NT     = 32 * (TN / 8);
    constexpr int K2     = 128;          // 256 k / 2
    constexpr int KC2    = 32;           // k-pairs per chunk (KC=64)
    constexpr int WROW2  = TN + 2;       // float2 units, even => 16B-alignable
    constexpr int AROW2  = TM + 2;

    extern __shared__ float2 smem2[];
    float2* Wc = smem2;                          // [K2][WROW2]
    float2* At = smem2 + K2 * WROW2;             // [2][KC2][AROW2]

    const int tid   = threadIdx.x;
    const int lane  = tid & 31;                  // rows lane*4..+3
    const int wid   = tid >> 5;                  // cols wid*8..+7
    const int node0 = blockIdx.x * TM;

    // Stage stacked weights, k-paired: Wc[k2][j] = (W[j][2k2], W[j][2k2+1])
    for (int idx = tid; idx < 64 * TN; idx += NT) {
        int j  = idx >> 6;
        int k2 = idx & 63;
        Wc[k2 * WROW2 + j]        = *(const float2*)(Wl + j * 128 + 2 * k2);
        Wc[(64 + k2) * WROW2 + j] = *(const float2*)(Wr + j * 128 + 2 * k2);
    }

    ull acc[4][8];
#pragma unroll
    for (int i = 0; i < 4; i++)
#pragma unroll
        for (int j = 0; j < 8; j++) acc[i][j] = 0ULL;

    auto loadA = [&](int buf, int kc) {
        float2* db = At + buf * (KC2 * AROW2);
#pragma unroll 4
        for (int idx = tid; idx < KC2 * TM; idx += NT) {
            int k2   = idx & (KC2 - 1);
            int node = idx >> 5;
            int k    = kc * 64 + 2 * k2;
            int n    = node0 + node;
            float2 v = make_float2(0.f, 0.f);
            if (n < N) {
                v = (k < 128) ? *(const float2*)(agg + (size_t)n * 128 + k)
                              : *(const float2*)(xin + (size_t)n * 128 + (k - 128));
            }
            db[k2 * AROW2 + node] = v;
        }
    };

    loadA(0, 0);
    __syncthreads();   // covers Wc too

#pragma unroll 1
    for (int kc = 0; kc < 4; kc++) {
        int b = kc & 1;
        if (kc < 3) loadA(b ^ 1, kc + 1);
        const float2* Ab = At + b * (KC2 * AROW2);
        const float2* Wb = Wc + (kc * KC2) * WROW2;
#pragma unroll 4
        for (int kk2 = 0; kk2 < KC2; kk2++) {
            const float2* ar = Ab + kk2 * AROW2 + lane * 4;
            const float2* wr = Wb + kk2 * WROW2 + wid * 8;
            ull a[4], w[8];
            {
                ulonglong2 t;
                t = *(const ulonglong2*)(ar);     a[0] = t.x; a[1] = t.y;
                t = *(const ulonglong2*)(ar + 2); a[2] = t.x; a[3] = t.y;
                t = *(const ulonglong2*)(wr);     w[0] = t.x; w[1] = t.y;
                t = *(const ulonglong2*)(wr + 2); w[2] = t.x; w[3] = t.y;
                t = *(const ulonglong2*)(wr + 4); w[4] = t.x; w[5] = t.y;
                t = *(const ulonglong2*)(wr + 6); w[6] = t.x; w[7] = t.y;
            }
#pragma unroll
            for (int i = 0; i < 4; i++)
#pragma unroll
                for (int j = 0; j < 8; j++) ffma2(acc[i][j], a[i], w[j]);
        }
        __syncthreads();
    }

    float bv[8];
#pragma unroll
    for (int j = 0; j < 8; j++) bv[j] = bias[wid * 8 + j];

#pragma unroll
    for (int i = 0; i < 4; i++) {
        int n = node0 + lane * 4 + i;
        if (n < N) {
            float r[8];
#pragma unroll
            for (int j = 0; j < 8; j++) {
                float2 p = *(float2*)&acc[i][j];
                float v  = p.x + p.y + bv[j];
                r[j] = do_relu ? fmaxf(v, 0.0f) : v;
            }
            *(float4*)(out + (size_t)n * TN + wid * 8)     = make_float4(r[0], r[1], r[2], r[3]);
            *(float4*)(out + (size_t)n * TN + wid * 8 + 4) = make_float4(r[4], r[5], r[6], r[7]);
        }
    }
}

// ---------------------------------------------------------------------------

extern "C" void kernel_launch(void* const* d_in, const int* in_sizes, int n_in,
                              void* d_out, int out_size) {
    const float* x   = (const float*)d_in[0];
    const void*  ei  = d_in[1];
    const float* Wl1 = (const float*)d_in[2];
    const float* bl1 = (const float*)d_in[3];
    const float* Wr1 = (const float*)d_in[4];
    const float* Wl2 = (const float*)d_in[5];
    const float* bl2 = (const float*)d_in[6];
    const float* Wr2 = (const float*)d_in[7];
    float* out = (float*)d_out;

    int N = in_sizes[0] / D_IN;
    int E = in_sizes[1] / 2;

    float *agg, *h;
    int *src, *dst, *bin, *cnt, *off, *cur, *bsum;
    cudaGetSymbolAddress((void**)&agg,  g_agg);
    cudaGetSymbolAddress((void**)&h,    g_h);
    cudaGetSymbolAddress((void**)&src,  g_src);
    cudaGetSymbolAddress((void**)&dst,  g_dst);
    cudaGetSymbolAddress((void**)&bin,  g_bin);
    cudaGetSymbolAddress((void**)&cnt,  g_cnt);
    cudaGetSymbolAddress((void**)&off,  g_off);
    cudaGetSymbolAddress((void**)&cur,  g_cur);
    cudaGetSymbolAddress((void**)&bsum, g_bsum);

    // smem bytes: (K2*WROW2 + 2*KC2*AROW2) float2
    constexpr int SMEM1 = (128 * (128 + 2) + 2 * 32 * (128 + 2)) * 8;  // 199680 B
    constexpr int SMEM2 = (128 * (64 + 2)  + 2 * 32 * (128 + 2)) * 8;  // 134144 B
    cudaFuncSetAttribute(sage_gemm_kernel<128>, cudaFuncAttributeMaxDynamicSharedMemorySize, SMEM1);
    cudaFuncSetAttribute(sage_gemm_kernel<64>,  cudaFuncAttributeMaxDynamicSharedMemorySize, SMEM2);

    const int TB = 256;
    int nbE = (E + TB - 1) / TB;
    int nbScan = (N + 1023) / 1024;

    // --- edge normalization + CSR binning (shared by both layers) ---
    detect_idx_kernel<<<1, 256>>>((const long long*)ei, E, (long long)N);
    convert_idx_kernel<<<nbE, TB>>>(ei, E, src, dst);
    cudaMemsetAsync(cnt, 0, (size_t)(N + 1) * sizeof(int));
    count_kernel<<<nbE, TB>>>(dst, cnt, E);
    scan_block_kernel<<<nbScan, 1024>>>(cnt, off, bsum, N);
    scan_bsum_kernel<<<1, 32>>>(bsum, nbScan);
    add_off_kernel<<<(N + TB - 1) / TB, TB>>>(off, bsum, N, E);
    cudaMemcpyAsync(cur, off, (size_t)(N + 1) * sizeof(int), cudaMemcpyDeviceToDevice);
    fill_kernel<<<nbE, TB>>>(src, dst, cur, bin, E);

    int nbGather = (N * 32 + TB - 1) / TB;

    // --- layer 1 ---
    gather_kernel<<<nbGather, TB>>>((const float4*)x, off, bin, (float4*)agg, N);
    sage_gemm_kernel<128><<<(N + 127) / 128, 512, SMEM1>>>(agg, x, Wl1, Wr1, bl1, h, N, 1);

    // --- layer 2 ---
    gather_kernel<<<nbGather, TB>>>((const float4*)h, off, bin, (float4*)agg, N);
    sage_gemm_kernel<64><<<(N + 127) / 128, 256, SMEM2>>>(agg, h, Wl2, Wr2, bl2, out, N, 0);
}